// round 4
// baseline (speedup 1.0000x reference)
#include <cuda_runtime.h>
#include <math.h>

// Dims
#define B_ 128
#define T_ 1024
#define I_ 256
#define H_ 512
#define O_ 256

typedef unsigned long long u64;

// Device scratch (static allocations are allowed)
__device__ __align__(16) float gW1t[768 * 512];   // [k][n] k: 0..511=h-k, 512..767=x-k
__device__ __align__(16) float gW2t[512 * 512];   // [k][n]  (Wih1+Whh1 combined, transposed)
__device__ __align__(16) float gW3t[512 * 256];   // [k][o]  (Wout transposed)
__device__ __align__(16) float g_h1[B_ * H_];
__device__ __align__(16) float g_h2[B_ * H_];

// ---------- f32x2 helpers ----------
__device__ __forceinline__ u64 pack2(float x, float y) {
    u64 r; asm("mov.b64 %0,{%1,%2};" : "=l"(r) : "f"(x), "f"(y)); return r;
}
__device__ __forceinline__ void unpack2(u64 p, float& x, float& y) {
    asm("mov.b64 {%0,%1},%2;" : "=f"(x), "=f"(y) : "l"(p));
}
__device__ __forceinline__ u64 fma2_(u64 a, u64 b, u64 c) {
    u64 d; asm("fma.rn.f32x2 %0,%1,%2,%3;" : "=l"(d) : "l"(a), "l"(b), "l"(c)); return d;
}
__device__ __forceinline__ u64 add2_(u64 a, u64 b) {
    u64 d; asm("add.rn.f32x2 %0,%1,%2;" : "=l"(d) : "l"(a), "l"(b)); return d;
}
__device__ __forceinline__ float mytanh(float x) {
    float xc = fminf(12.f, fmaxf(-12.f, x));
    float e = __expf(2.f * xc);
    return __fdividef(e - 1.f, e + 1.f);
}
__device__ __forceinline__ void cluster_sync_all() {
    __threadfence();  // make .cg global stores visible before arrive
    asm volatile("barrier.cluster.arrive.aligned;" ::: "memory");
    asm volatile("barrier.cluster.wait.aligned;" ::: "memory");
}

// ---------- SMEM layout (floats) ----------
// W2S : [0, 32768)        512 x 64  (Wc slice, k-major)
// W3S : [32768, 49152)    512 x 32  (Wout slice, k-major)
// AS  : [49152, 56832)    768 rows x 10 (cols m=0..7 + 2 pad) activation staging
//       scratchAB aliases AS[0..4608)   (256 thr x 18)
//       scratchC  aliases AS[5120..7680) (x region; 256 thr x 10)
// bias: [56832, 56992)
#define W2S_OFF 0
#define W3S_OFF 32768
#define AS_OFF  49152
#define B0_OFF  56832
#define BC_OFF  56896
#define BO_OFF  56960
#define SMEM_FLOATS 56992
#define SMEM_BYTES (SMEM_FLOATS * 4)

// ---------- prep kernel: transpose / combine weights ----------
__global__ void rnn_prep(const float* __restrict__ Wih0, const float* __restrict__ Whh0,
                         const float* __restrict__ Wih1, const float* __restrict__ Whh1,
                         const float* __restrict__ Wout) {
    int i = blockIdx.x * blockDim.x + threadIdx.x;
    if (i < 768 * 512) {
        int k = i >> 9, n = i & 511;
        gW1t[i] = (k < 512) ? Whh0[n * 512 + k] : Wih0[n * 256 + (k - 512)];
    }
    if (i < 512 * 512) {
        int k = i >> 9, n = i & 511;
        gW2t[i] = Wih1[n * 512 + k] + Whh1[n * 512 + k];
    }
    if (i < 512 * 256) {
        int k = i >> 8, o = i & 255;
        gW3t[i] = Wout[o * 512 + k];
    }
}

// ---------- staging helpers ----------
__device__ __forceinline__ void stage_h(float* as_, const float* src, int grp8, int tid) {
#pragma unroll
    for (int m = 0; m < 8; m++) {
        const float* row = src + (grp8 + m) * 512;
#pragma unroll
        for (int kk = 0; kk < 2; kk++) {
            int k = tid + kk * 256;
            as_[k * 10 + m] = __ldcg(row + k);
        }
    }
}
__device__ __forceinline__ void stage_x(float* as_, const float* x, int grp8, int t, int tid) {
#pragma unroll
    for (int m = 0; m < 8; m++) {
        const float* base = x + ((size_t)(grp8 + m) * T_ + t) * I_;
        as_[(512 + tid) * 10 + m] = __ldg(base + tid);
    }
}

// ---------- main persistent kernel ----------
__global__ void __launch_bounds__(256, 1) __cluster_dims__(8, 1, 1)
rnn_main(const float* __restrict__ x, const float* __restrict__ h0,
         const float* __restrict__ bih0, const float* __restrict__ bhh0,
         const float* __restrict__ bih1, const float* __restrict__ bhh1,
         const float* __restrict__ bout, float* __restrict__ out) {
    extern __shared__ float smem[];
    float* W2S = smem + W2S_OFF;
    float* W3S = smem + W3S_OFF;
    float* as_ = smem + AS_OFF;
    float* b0s = smem + B0_OFF;
    float* bcs = smem + BC_OFF;
    float* bos = smem + BO_OFF;

    const int tid = threadIdx.x;
    const int grp = blockIdx.x >> 3;      // batch group (16)
    const int rank = blockIdx.x & 7;      // cluster rank: H/O column slice
    const int grp8 = grp * 8;             // first batch row of group
    const int nb = rank * 64;             // hidden-col base
    const int ob = rank * 32;             // output-col base

    const int kp = tid >> 5;              // k-part (warp) 0..7
    const int ng = tid & 31;              // n-group within warp

    // ---- load resident weight slices into SMEM (k-major, straight copy) ----
    for (int i = tid; i < 512 * 64; i += 256) {
        int k = i >> 6, j = i & 63;
        W2S[i] = gW2t[k * 512 + nb + j];
    }
    for (int i = tid; i < 512 * 32; i += 256) {
        int k = i >> 5, j = i & 31;
        W3S[i] = gW3t[k * 256 + ob + j];
    }
    if (tid < 64) b0s[tid] = bih0[nb + tid] + bhh0[nb + tid];
    if (tid < 64) bcs[tid] = bih1[nb + tid] + bhh1[nb + tid];
    if (tid < 32) bos[tid] = bout[ob + tid];

    // ---- initial staging: h_prev = h0, x_0 ----
    stage_h(as_, h0, grp8, tid);
    stage_x(as_, x, grp8, 0, tid);

    for (int t = 0; t < T_; t++) {
        __syncthreads();  // staging (h/x) visible before phase A reads

        // ================= Phase A: h1 = tanh([h;x] @ W1^T + b0) =================
        // thread: 4 m-pairs x 2 n-cols, K-slice 96 (kp of 8)
        u64 acc[8];
#pragma unroll
        for (int j = 0; j < 8; j++) acc[j] = 0ull;
        {
            const int kbase = kp * 96;
            const float2* __restrict__ wp =
                reinterpret_cast<const float2*>(gW1t) + (size_t)kbase * 256 + rank * 32 + ng;
            const float* asb = as_ + kbase * 10;
            float2 wreg[8];
#pragma unroll
            for (int i = 0; i < 8; i++) wreg[i] = __ldg(wp + (size_t)i * 256);
#pragma unroll 2
            for (int kk = 0; kk < 96; kk += 8) {
#pragma unroll
                for (int i = 0; i < 8; i++) {
                    float2 wv = wreg[i];
                    int kn = kk + 8 + i;
                    if (kn < 96) wreg[i] = __ldg(wp + (size_t)kn * 256);
                    const float* ar = asb + (kk + i) * 10;
                    u64 wa = pack2(wv.x, wv.x);
                    u64 wb = pack2(wv.y, wv.y);
#pragma unroll
                    for (int mp = 0; mp < 4; mp++) {
                        u64 ap = *reinterpret_cast<const u64*>(ar + mp * 2);
                        acc[mp * 2]     = fma2_(ap, wa, acc[mp * 2]);
                        acc[mp * 2 + 1] = fma2_(ap, wb, acc[mp * 2 + 1]);
                    }
                }
            }
        }
        __syncthreads();  // all K-loop reads done; scratch aliases AS
        {
            float* scr = as_;  // stride 18
#pragma unroll
            for (int j = 0; j < 8; j++)
                *reinterpret_cast<u64*>(scr + tid * 18 + j * 2) = acc[j];
        }
        __syncthreads();
        {   // reduce over 8 k-parts, tanh, publish h1 slice
            const float* scr = as_;
            int n = tid & 63, mp = tid >> 6;
            const float* base = scr + (n >> 1) * 18 + (mp * 2 + (n & 1)) * 2;
            u64 s = *reinterpret_cast<const u64*>(base);
#pragma unroll
            for (int k2 = 1; k2 < 8; k2++)
                s = add2_(s, *reinterpret_cast<const u64*>(base + k2 * (32 * 18)));
            float v0, v1; unpack2(s, v0, v1);
            float bb = b0s[n];
            v0 = mytanh(v0 + bb); v1 = mytanh(v1 + bb);
            int col = nb + n, row = grp8 + mp * 2;
            __stcg(&g_h1[row * 512 + col], v0);
            __stcg(&g_h1[(row + 1) * 512 + col], v1);
        }
        cluster_sync_all();  // #1

        // ================= Phase B: h2 = tanh(h1 @ Wc^T + bc) =================
        stage_h(as_, g_h1, grp8, tid);
        __syncthreads();
#pragma unroll
        for (int j = 0; j < 8; j++) acc[j] = 0ull;
        {
            const int kbase = kp * 64;
            const float* wsb = W2S + kbase * 64 + ng * 2;
            const float* asb = as_ + kbase * 10;
#pragma unroll 8
            for (int kk = 0; kk < 64; kk++) {
                float2 wv = *reinterpret_cast<const float2*>(wsb + kk * 64);
                const float* ar = asb + kk * 10;
                u64 wa = pack2(wv.x, wv.x);
                u64 wb = pack2(wv.y, wv.y);
#pragma unroll
                for (int mp = 0; mp < 4; mp++) {
                    u64 ap = *reinterpret_cast<const u64*>(ar + mp * 2);
                    acc[mp * 2]     = fma2_(ap, wa, acc[mp * 2]);
                    acc[mp * 2 + 1] = fma2_(ap, wb, acc[mp * 2 + 1]);
                }
            }
        }
        __syncthreads();
        {
            float* scr = as_;
#pragma unroll
            for (int j = 0; j < 8; j++)
                *reinterpret_cast<u64*>(scr + tid * 18 + j * 2) = acc[j];
        }
        __syncthreads();
        {
            const float* scr = as_;
            int n = tid & 63, mp = tid >> 6;
            const float* base = scr + (n >> 1) * 18 + (mp * 2 + (n & 1)) * 2;
            u64 s = *reinterpret_cast<const u64*>(base);
#pragma unroll
            for (int k2 = 1; k2 < 8; k2++)
                s = add2_(s, *reinterpret_cast<const u64*>(base + k2 * (32 * 18)));
            float v0, v1; unpack2(s, v0, v1);
            float bb = bcs[n];
            v0 = mytanh(v0 + bb); v1 = mytanh(v1 + bb);
            int col = nb + n, row = grp8 + mp * 2;
            __stcg(&g_h2[row * 512 + col], v0);
            __stcg(&g_h2[(row + 1) * 512 + col], v1);
        }
        cluster_sync_all();  // #2

        // ================= Phase C: y = h2 @ Wout^T + b_out =================
        stage_h(as_, g_h2, grp8, tid);  // also serves next step's phase A
        __syncthreads();
        u64 accc[4];
#pragma unroll
        for (int j = 0; j < 4; j++) accc[j] = 0ull;
        {
            const int kbase = kp * 64;
            const float* wsb = W3S + kbase * 32 + ng;  // 1 n-col per thread
            const float* asb = as_ + kbase * 10;
#pragma unroll 8
            for (int kk = 0; kk < 64; kk++) {
                float w = wsb[kk * 32];
                const float* ar = asb + kk * 10;
                u64 wa = pack2(w, w);
#pragma unroll
                for (int mp = 0; mp < 4; mp++) {
                    u64 ap = *reinterpret_cast<const u64*>(ar + mp * 2);
                    accc[mp] = fma2_(ap, wa, accc[mp]);
                }
            }
        }
        __syncthreads();
        {
            float* scrC = as_ + 5120;  // x region (dead), stride 10
#pragma unroll
            for (int j = 0; j < 4; j++)
                *reinterpret_cast<u64*>(scrC + tid * 10 + j * 2) = accc[j];
        }
        __syncthreads();
        if (tid < 128) {
            const float* scrC = as_ + 5120;
            int n = tid & 31, mp = tid >> 5;
            const float* base = scrC + n * 10 + mp * 2;
            u64 s = *reinterpret_cast<const u64*>(base);
#pragma unroll
            for (int k2 = 1; k2 < 8; k2++)
                s = add2_(s, *reinterpret_cast<const u64*>(base + k2 * (32 * 10)));
            float v0, v1; unpack2(s, v0, v1);
            float bb = bos[n];
            v0 += bb; v1 += bb;
            int o = ob + n, row = grp8 + mp * 2;
            out[(size_t)row * (T_ * O_) + (size_t)t * O_ + o] = v0;
            out[(size_t)(row + 1) * (T_ * O_) + (size_t)t * O_ + o] = v1;
        }
        __syncthreads();  // scratchC reads done before x staging overwrites region

        // stage x_{t+1} (clamped; unused garbage-free)
        int tn = (t + 1 < T_) ? (t + 1) : t;
        stage_x(as_, x, grp8, tn, tid);
    }
}

extern "C" void kernel_launch(void* const* d_in, const int* in_sizes, int n_in,
                              void* d_out, int out_size) {
    const float* x    = (const float*)d_in[0];
    const float* h0   = (const float*)d_in[1];
    const float* Wih0 = (const float*)d_in[2];
    const float* bih0 = (const float*)d_in[3];
    const float* Whh0 = (const float*)d_in[4];
    const float* bhh0 = (const float*)d_in[5];
    const float* Wih1 = (const float*)d_in[6];
    const float* bih1 = (const float*)d_in[7];
    const float* Whh1 = (const float*)d_in[8];
    const float* bhh1 = (const float*)d_in[9];
    const float* Wout = (const float*)d_in[10];
    const float* bout = (const float*)d_in[11];
    float* out = (float*)d_out;

    cudaFuncSetAttribute(rnn_main, cudaFuncAttributeMaxDynamicSharedMemorySize, SMEM_BYTES);

    rnn_prep<<<(768 * 512 + 255) / 256, 256>>>(Wih0, Whh0, Wih1, Whh1, Wout);
    rnn_main<<<128, 256, SMEM_BYTES>>>(x, h0, bih0, bhh0, bih1, bhh1, bout, out);
}